// round 9
// baseline (speedup 1.0000x reference)
#include <cuda_runtime.h>
#include <cuda_bf16.h>
#include <cstdint>
#include <cstring>

#define L1N 1024
#define DN  512
#define G4  2048

__device__ float d_buf0[1024 * 1024];
__device__ float d_buf1[1024 * 1024];
__device__ float d_A[2 * 1024 * 2048];
__device__ float d_mu[1024 * 512];
__device__ float d_ps[1024 * 512];
__device__ float d_z[1024 * 512];
__device__ float d_pos[1024];
__device__ float d_neg[1024];
__device__ float d_negf[1024];
__device__ double d_kl[1];
__device__ double d_sumy[1];

__device__ __nv_bfloat16 b_Wb[2 * 2048 * 1024];
__device__ __nv_bfloat16 b_Xb[1024 * 1024];
__device__ __nv_bfloat16 b_Gen[8192 * 512];
__device__ __nv_bfloat16 b_Gfrn[8192 * 512];
__device__ __nv_bfloat16 b_Gfr[1024 * 512];
__device__ __nv_bfloat16 b_zb[1024 * 512];
__device__ __nv_bfloat16 b_hb[1024 * 512];
__device__ __nv_bfloat16 b_t1[1024 * 512];
__device__ __nv_bfloat16 b_t2[1024 * 512];
__device__ __nv_bfloat16 b_Wm[4 * 512 * 512];

__device__ __forceinline__ float sigm_f(float x) { return 1.f / (1.f + __expf(-x)); }
__device__ __forceinline__ float tanh_f(float x) {
    if (x > 10.f) return 1.f;
    if (x < -10.f) return -1.f;
    float e = __expf(2.f * x);
    return (e - 1.f) / (e + 1.f);
}
__device__ __forceinline__ uint32_t smem_u32(const void* p) {
    uint32_t a;
    asm("{ .reg .u64 t; cvta.to.shared.u64 t, %1; cvt.u32.u64 %0, t; }" : "=r"(a) : "l"(p));
    return a;
}
__device__ __forceinline__ __nv_bfloat162 as_bf2(uint32_t v) {
    __nv_bfloat162 r; memcpy(&r, &v, 4); return r;
}
__device__ __forceinline__ uint32_t packbf(float a, float b) {
    __nv_bfloat162 t = __float22bfloat162_rn(make_float2(a, b));
    uint32_t v; memcpy(&v, &t, 4); return v;
}
__device__ __forceinline__ void bar_wait_cl(uint32_t addr, uint32_t par) {
    uint32_t done;
    do {
        asm volatile("{\n\t.reg .pred p;\n\t"
            "mbarrier.try_wait.parity.acquire.cluster.shared::cta.b64 p, [%1], %2, 0x989680;\n\t"
            "selp.b32 %0, 1, 0, p;\n\t}"
            : "=r"(done) : "r"(addr), "r"(par) : "memory");
    } while (!done);
}
__device__ __forceinline__ void arrive_peer(uint32_t addr, uint32_t rank) {
    asm volatile("{\n\t.reg .b32 ra;\n\t"
        "mapa.shared::cluster.u32 ra, %0, %1;\n\t"
        "mbarrier.arrive.shared::cluster.b64 _, [ra];\n\t}"
        :: "r"(addr), "r"(rank) : "memory");
}
__device__ __forceinline__ void st_peer_v4(uint32_t addr, uint32_t peer, uint4 v) {
    asm volatile("{\n\t.reg .b32 ra;\n\t"
        "mapa.shared::cluster.u32 ra, %0, %1;\n\t"
        "st.shared::cluster.v4.u32 [ra], {%2,%3,%4,%5};\n\t}"
        :: "r"(addr), "r"(peer), "r"(v.x), "r"(v.y), "r"(v.z), "r"(v.w) : "memory");
}
__device__ __forceinline__ void ldsm_x4(uint32_t& r0, uint32_t& r1, uint32_t& r2, uint32_t& r3, uint32_t addr) {
    asm volatile("ldmatrix.sync.aligned.m8n8.x4.shared.b16 {%0,%1,%2,%3}, [%4];"
        : "=r"(r0), "=r"(r1), "=r"(r2), "=r"(r3) : "r"(addr));
}
__device__ __forceinline__ void ldsm_x2(uint32_t& r0, uint32_t& r1, uint32_t addr) {
    asm volatile("ldmatrix.sync.aligned.m8n8.x2.shared.b16 {%0,%1}, [%2];"
        : "=r"(r0), "=r"(r1) : "r"(addr));
}
__device__ __forceinline__ void mma16816(float* d, const uint32_t* a, const uint32_t* b) {
    asm volatile("mma.sync.aligned.m16n8k16.row.col.f32.bf16.bf16.f32 "
        "{%0,%1,%2,%3}, {%4,%5,%6,%7}, {%8,%9}, {%0,%1,%2,%3};"
        : "+f"(d[0]), "+f"(d[1]), "+f"(d[2]), "+f"(d[3])
        : "r"(a[0]), "r"(a[1]), "r"(a[2]), "r"(a[3]), "r"(b[0]), "r"(b[1]));
}

__global__ void reset_kernel() {
    int i = blockIdx.x * 256 + threadIdx.x;
    if (i < 1024) { d_neg[i] = 0.f; d_negf[i] = 0.f; }
    if (i == 0) { d_kl[0] = 0.0; d_sumy[0] = 0.0; }
}

__global__ void gatherb_kernel(const float* __restrict__ E, const int* __restrict__ idx,
                               __nv_bfloat16* __restrict__ dst) {
    int r = blockIdx.x, t = threadIdx.x;  // 128 threads
    float4 v = *(const float4*)(E + (size_t)idx[r] * 512 + t * 4);
    ((uint2*)(dst + (size_t)r * 512))[t] = make_uint2(packbf(v.x, v.y), packbf(v.z, v.w));
}

__global__ void convb_kernel(const float* __restrict__ src, __nv_bfloat16* __restrict__ dst, int n4) {
    int i = blockIdx.x * 256 + threadIdx.x;
    if (i < n4) {
        float4 v = ((const float4*)src)[i];
        ((uint2*)dst)[i] = make_uint2(packbf(v.x, v.y), packbf(v.z, v.w));
    }
}

__global__ void hsum_kernel(__nv_bfloat16* __restrict__ hb) {
    int i = blockIdx.x * 256 + threadIdx.x;  // 524288
    int t = i >> 9, d = i & 511;
    hb[i] = __float2bfloat16(d_buf1[t * 1024 + d] + d_buf1[t * 1024 + 512 + d]);
}

// bf16 tensor-core GEMM: C[M][N] = A[M][K] @ B[N][K]^T (fp32 accum)
__global__ __launch_bounds__(256) void gemm_bf16_kernel(
    const __nv_bfloat16* __restrict__ A, int lda,
    const __nv_bfloat16* __restrict__ B, int ldb,
    const float* __restrict__ bias,
    float* __restrict__ C, __nv_bfloat16* __restrict__ Cb, int ldc,
    int K, int mode,
    const float* __restrict__ negf,
    float* __restrict__ rowsum,
    double* __restrict__ outsum)
{
    __shared__ __align__(16) __nv_bfloat16 As[64][40];
    __shared__ __align__(16) __nv_bfloat16 Bs[64][40];
    __shared__ float red[256];

    int tid = threadIdx.x;
    int wid = tid >> 5, lane = tid & 31;
    int m0 = blockIdx.y * 64, n0 = blockIdx.x * 64;
    int wm = (wid & 1) * 32, wn = (wid >> 1) * 16;
    int lr = tid >> 2, ls = (tid & 3) * 8;

    float acc[2][2][4] = {};

    uint32_t a_addr[2], b_addr[2];
    #pragma unroll
    for (int i = 0; i < 2; ++i)
        a_addr[i] = smem_u32(&As[wm + i * 16 + (lane & 15)][(lane >> 4) * 8]);
    #pragma unroll
    for (int j = 0; j < 2; ++j)
        b_addr[j] = smem_u32(&Bs[wn + j * 8 + (lane & 7)][((lane >> 3) & 1) * 8]);

    for (int k0 = 0; k0 < K; k0 += 32) {
        *(uint4*)&As[lr][ls] = *(const uint4*)(A + (size_t)(m0 + lr) * lda + k0 + ls);
        *(uint4*)&Bs[lr][ls] = *(const uint4*)(B + (size_t)(n0 + lr) * ldb + k0 + ls);
        __syncthreads();
        #pragma unroll
        for (int kk = 0; kk < 2; ++kk) {
            uint32_t af[2][4], bf[2][2];
            #pragma unroll
            for (int i = 0; i < 2; ++i)
                ldsm_x4(af[i][0], af[i][1], af[i][2], af[i][3], a_addr[i] + kk * 32);
            #pragma unroll
            for (int j = 0; j < 2; ++j)
                ldsm_x2(bf[j][0], bf[j][1], b_addr[j] + kk * 32);
            #pragma unroll
            for (int i = 0; i < 2; ++i)
                #pragma unroll
                for (int j = 0; j < 2; ++j)
                    mma16816(acc[i][j], af[i], bf[j]);
        }
        __syncthreads();
    }

    int qr = lane >> 2, qc = (lane & 3) * 2;
    if (mode <= 1) {
        #pragma unroll
        for (int i = 0; i < 2; ++i)
            #pragma unroll
            for (int r = 0; r < 2; ++r) {
                int row = m0 + wm + i * 16 + r * 8 + qr;
                #pragma unroll
                for (int j = 0; j < 2; ++j) {
                    int col = n0 + wn + j * 8 + qc;
                    float v0 = acc[i][j][r * 2 + 0] + (bias ? bias[col] : 0.f);
                    float v1 = acc[i][j][r * 2 + 1] + (bias ? bias[col + 1] : 0.f);
                    if (mode == 1) { v0 = fmaxf(v0, 0.f); v1 = fmaxf(v1, 0.f); }
                    if (C) *(float2*)(C + (size_t)row * ldc + col) = make_float2(v0, v1);
                    if (Cb) *(uint32_t*)(Cb + (size_t)row * ldc + col) = packbf(v0, v1);
                }
            }
    } else if (mode == 2) {
        #pragma unroll
        for (int i = 0; i < 2; ++i)
            #pragma unroll
            for (int r = 0; r < 2; ++r) {
                float s = 0.f;
                #pragma unroll
                for (int j = 0; j < 2; ++j)
                    s += __expf(acc[i][j][r * 2]) + __expf(acc[i][j][r * 2 + 1]);
                s += __shfl_xor_sync(0xffffffffu, s, 1);
                s += __shfl_xor_sync(0xffffffffu, s, 2);
                if ((lane & 3) == 0)
                    atomicAdd(rowsum + m0 + wm + i * 16 + r * 8 + qr, s);
            }
    } else {
        float ssum = 0.f;
        #pragma unroll
        for (int i = 0; i < 2; ++i)
            #pragma unroll
            for (int r = 0; r < 2; ++r) {
                float nf = negf[m0 + wm + i * 16 + r * 8 + qr];
                #pragma unroll
                for (int j = 0; j < 2; ++j) {
                    float e0 = __expf(acc[i][j][r * 2]);
                    float e1 = __expf(acc[i][j][r * 2 + 1]);
                    ssum += e0 / (e0 + nf) + e1 / (e1 + nf);
                }
            }
        red[tid] = ssum;
        __syncthreads();
        for (int st = 128; st > 0; st >>= 1) {
            if (tid < st) red[tid] += red[tid + st];
            __syncthreads();
        }
        if (tid == 0) atomicAdd(outsum, (double)red[0]);
    }
}

// Cluster scan: grid 32, cluster 16. dir = bx>>4, rank owns hidden [32r,32r+32).
// Tiling: col-group g = lane&7 owns cols [64g,64g+64); rows = 16w + 4*(lane>>3) + j.
__global__ __launch_bounds__(256, 1) void lstm_scan_cluster(
    const float* __restrict__ Whh, const float* __restrict__ Agate,
    float* __restrict__ outbuf)
{
    __shared__ uint32_t sh_hp[2][256];
    __shared__ float sh_g[128];
    __shared__ __align__(16) uint32_t sh_w[16];
    __shared__ __align__(8) uint64_t sh_bar;

    const int tid = threadIdx.x;
    const int w = tid >> 5, lane = tid & 31;
    const int g = lane & 7, sub = lane >> 3;
    uint32_t rank;
    asm("mov.u32 %0, %%cluster_ctarank;" : "=r"(rank));
    const int dir = blockIdx.x >> 4;
    const bool fwd = (dir == 0);
    const float* Wd = Whh + (size_t)dir * G4 * DN;
    const float* Ad = Agate + (size_t)dir * L1N * G4;

    const uint32_t bar_addr = smem_u32(&sh_bar);
    const uint32_t hp0 = smem_u32(&sh_hp[0][0]);
    const uint32_t hp1 = smem_u32(&sh_hp[1][0]);

    if (tid == 0)
        asm volatile("mbarrier.init.shared.b64 [%0], %1;" :: "r"(bar_addr), "r"(16u) : "memory");
    sh_hp[1][tid] = 0u;

    int grow_j[4];
    uint32_t wp[4][32];
    #pragma unroll
    for (int j = 0; j < 4; ++j) {
        int row = 16 * w + 4 * sub + j;
        grow_j[j] = (row >> 5) * 512 + rank * 32 + (row & 31);
        const float* src = Wd + (size_t)grow_j[j] * DN + g * 64;
        #pragma unroll
        for (int q = 0; q < 16; ++q) {
            float4 v = *(const float4*)(src + q * 4);
            wp[j][2 * q]     = packbf(v.x, v.y);
            wp[j][2 * q + 1] = packbf(v.z, v.w);
        }
    }
    __syncthreads();
    asm volatile("barrier.cluster.arrive.aligned;" ::: "memory");
    asm volatile("barrier.cluster.wait.aligned;" ::: "memory");

    float c_state = 0.f;
    uint32_t parity = 0;

    for (int s = 0; s < L1N; ++s) {
        int t = fwd ? s : (L1N - 1 - s);

        float bias[4];
        if (g == 0) {
            #pragma unroll
            for (int j = 0; j < 4; ++j)
                bias[j] = Ad[(size_t)t * G4 + grow_j[j]];
        }

        if (s > 0) { bar_wait_cl(bar_addr, parity); parity ^= 1; }

        int rb = (s + 1) & 1;
        uint32_t hvp[32];
        #pragma unroll
        for (int q = 0; q < 8; ++q) {
            uint4 v = *(const uint4*)&sh_hp[rb][g * 32 + q * 4];
            hvp[4 * q + 0] = v.x; hvp[4 * q + 1] = v.y;
            hvp[4 * q + 2] = v.z; hvp[4 * q + 3] = v.w;
        }

        #pragma unroll
        for (int j = 0; j < 4; ++j) {
            __nv_bfloat162 a0 = __float2bfloat162_rn(0.f), a1 = a0, a2 = a0, a3 = a0;
            #pragma unroll
            for (int k = 0; k < 32; k += 4) {
                a0 = __hfma2(as_bf2(wp[j][k]),     as_bf2(hvp[k]),     a0);
                a1 = __hfma2(as_bf2(wp[j][k + 1]), as_bf2(hvp[k + 1]), a1);
                a2 = __hfma2(as_bf2(wp[j][k + 2]), as_bf2(hvp[k + 2]), a2);
                a3 = __hfma2(as_bf2(wp[j][k + 3]), as_bf2(hvp[k + 3]), a3);
            }
            a0 = __hadd2(a0, a1); a2 = __hadd2(a2, a3); a0 = __hadd2(a0, a2);
            float sv = __low2float(a0) + __high2float(a0);
            sv += __shfl_xor_sync(0xffffffffu, sv, 1);
            sv += __shfl_xor_sync(0xffffffffu, sv, 2);
            sv += __shfl_xor_sync(0xffffffffu, sv, 4);
            if (g == 0) sh_g[16 * w + 4 * sub + j] = sv + bias[j];
        }
        __syncthreads();

        if (w == 0) {
            float iv = sigm_f(sh_g[lane]);
            float fv = sigm_f(sh_g[32 + lane]);
            float gv = tanh_f(sh_g[64 + lane]);
            float ov = sigm_f(sh_g[96 + lane]);
            c_state = fv * c_state + iv * gv;
            float h = ov * tanh_f(c_state);

            float fe = __shfl_sync(0xffffffffu, h, 2 * (lane & 15));
            float fo = __shfl_sync(0xffffffffu, h, 2 * (lane & 15) + 1);
            if (lane < 16) sh_w[lane] = packbf(fe, fo);
            outbuf[(size_t)t * 1024 + dir * 512 + rank * 32 + lane] = h;
        }
        __syncthreads();

        if (tid < 64) {
            int peer = tid >> 2, q = tid & 3;
            uint4 val = ((const uint4*)sh_w)[q];
            uint32_t dst = ((s & 1) ? hp1 : hp0) + (rank * 16 + q * 4) * 4;
            st_peer_v4(dst, (uint32_t)peer, val);
        }
        __syncthreads();
        if (tid < 16) arrive_peer(bar_addr, (uint32_t)tid);
    }
    asm volatile("barrier.cluster.arrive.aligned;" ::: "memory");
    asm volatile("barrier.cluster.wait.aligned;" ::: "memory");
}

__global__ void zkl_kernel(const float* __restrict__ eps, __nv_bfloat16* __restrict__ zb) {
    int i = blockIdx.x * 256 + threadIdx.x;
    float m = d_mu[i], pre = d_ps[i];
    float sg = log1pf(expf(pre));
    float zv = fmaf(eps[i], sg, m);
    d_z[i] = zv;
    zb[i] = __float2bfloat16(zv);
    float term = 0.5f * (sg * sg + m * m - 1.f) - logf(sg);
    __shared__ float red[256];
    red[threadIdx.x] = term;
    __syncthreads();
    for (int st = 128; st > 0; st >>= 1) {
        if (threadIdx.x < st) red[threadIdx.x] += red[threadIdx.x + st];
        __syncthreads();
    }
    if (threadIdx.x == 0) atomicAdd(d_kl, (double)red[0]);
}

__global__ void pos_kernel(const int* __restrict__ en, const float* __restrict__ E) {
    int t = blockIdx.x, tid = threadIdx.x;
    float4 a = *(const float4*)(d_z + t * DN + tid * 4);
    float4 b = *(const float4*)(E + (size_t)en[t] * DN + tid * 4);
    float s = a.x * b.x + a.y * b.y + a.z * b.z + a.w * b.w;
    #pragma unroll
    for (int off = 16; off > 0; off >>= 1) s += __shfl_xor_sync(0xffffffffu, s, off);
    __shared__ float red[4];
    if ((tid & 31) == 0) red[tid >> 5] = s;
    __syncthreads();
    if (tid == 0) d_pos[t] = expf(red[0] + red[1] + red[2] + red[3]);
}

__global__ void final_kernel(float* __restrict__ out) {
    int tid = threadIdx.x;
    float sx = 0.f;
    for (int t = tid; t < 1024; t += 256) {
        float pv = d_pos[t];
        sx += pv / (pv + d_neg[t]);
    }
    __shared__ float red[256];
    red[tid] = sx;
    __syncthreads();
    for (int st = 128; st > 0; st >>= 1) {
        if (tid < st) red[tid] += red[tid + st];
        __syncthreads();
    }
    if (tid == 0) {
        float sum_y = (float)(d_sumy[0] / 1024.0);
        out[0] = -(red[0] + sum_y - (float)d_kl[0]);
    }
}

extern "C" void kernel_launch(void* const* d_in, const int* in_sizes, int n_in,
                              void* d_out, int out_size)
{
    (void)in_sizes; (void)n_in; (void)out_size;
    const int*   en     = (const int*)d_in[0];
    const int*   fr     = (const int*)d_in[1];
    const int*   en_neg = (const int*)d_in[2];
    const int*   fr_neg = (const int*)d_in[3];
    const float* emb    = (const float*)d_in[4];
    const float* Wih[3] = {(const float*)d_in[5], (const float*)d_in[8], (const float*)d_in[11]};
    const float* Whh[3] = {(const float*)d_in[6], (const float*)d_in[9], (const float*)d_in[12]};
    const float* bb[3]  = {(const float*)d_in[7], (const float*)d_in[10], (const float*)d_in[13]};
    const float* Wmu1 = (const float*)d_in[14];
    const float* bmu1 = (const float*)d_in[15];
    const float* Wmu2 = (const float*)d_in[16];
    const float* bmu2 = (const float*)d_in[17];
    const float* Ws1  = (const float*)d_in[18];
    const float* bs1  = (const float*)d_in[19];
    const float* Ws2  = (const float*)d_in[20];
    const float* bs2  = (const float*)d_in[21];
    const float* E_en = (const float*)d_in[22];
    const float* E_fr = (const float*)d_in[23];
    const float* eps  = (const float*)d_in[24];

    float *buf0, *buf1, *Abuf, *mu, *ps, *z, *negp, *negfp;
    double *sumy;
    __nv_bfloat16 *Wb, *Xb, *Gen, *Gfrn, *Gfr, *zb, *hb, *t1b, *t2b, *Wm;
    cudaGetSymbolAddress((void**)&buf0, d_buf0);
    cudaGetSymbolAddress((void**)&buf1, d_buf1);
    cudaGetSymbolAddress((void**)&Abuf, d_A);
    cudaGetSymbolAddress((void**)&mu, d_mu);
    cudaGetSymbolAddress((void**)&ps, d_ps);
    cudaGetSymbolAddress((void**)&z, d_z);
    cudaGetSymbolAddress((void**)&negp, d_neg);
    cudaGetSymbolAddress((void**)&negfp, d_negf);
    cudaGetSymbolAddress((void**)&sumy, d_sumy);
    cudaGetSymbolAddress((void**)&Wb, b_Wb);
    cudaGetSymbolAddress((void**)&Xb, b_Xb);
    cudaGetSymbolAddress((void**)&Gen, b_Gen);
    cudaGetSymbolAddress((void**)&Gfrn, b_Gfrn);
    cudaGetSymbolAddress((void**)&Gfr, b_Gfr);
    cudaGetSymbolAddress((void**)&zb, b_zb);
    cudaGetSymbolAddress((void**)&hb, b_hb);
    cudaGetSymbolAddress((void**)&t1b, b_t1);
    cudaGetSymbolAddress((void**)&t2b, b_t2);
    cudaGetSymbolAddress((void**)&Wm, b_Wm);

    cudaFuncSetAttribute(lstm_scan_cluster,
                         cudaFuncAttributeNonPortableClusterSizeAllowed, 1);

    reset_kernel<<<4, 256>>>();
    gatherb_kernel<<<1024, 128>>>(emb, en, Xb);
    gatherb_kernel<<<8192, 128>>>(E_en, en_neg, Gen);
    gatherb_kernel<<<8192, 128>>>(E_fr, fr_neg, Gfrn);
    gatherb_kernel<<<1024, 128>>>(E_fr, fr, Gfr);

    float* outb[3] = {buf1, buf0, buf1};
    int    Kl[3]   = {512, 1024, 1024};
    for (int l = 0; l < 3; ++l) {
        if (l > 0)
            convb_kernel<<<1024, 256>>>(outb[l - 1], Xb, 1024 * 1024 / 4);
        convb_kernel<<<(2 * 2048 * Kl[l] / 4 + 255) / 256, 256>>>(Wih[l], Wb, 2 * 2048 * Kl[l] / 4);
        for (int d = 0; d < 2; ++d) {
            gemm_bf16_kernel<<<dim3(32, 16), 256>>>(
                Xb, Kl[l], Wb + (size_t)d * 2048 * Kl[l], Kl[l],
                bb[l] + d * 2048,
                Abuf + (size_t)d * 1024 * 2048, nullptr, 2048, Kl[l], 0,
                nullptr, nullptr, nullptr);
        }
        cudaLaunchConfig_t cfg = {};
        cfg.gridDim = dim3(32, 1, 1);
        cfg.blockDim = dim3(256, 1, 1);
        cfg.dynamicSmemBytes = 0;
        cfg.stream = 0;
        cudaLaunchAttribute at[1];
        at[0].id = cudaLaunchAttributeClusterDimension;
        at[0].val.clusterDim.x = 16;
        at[0].val.clusterDim.y = 1;
        at[0].val.clusterDim.z = 1;
        cfg.attrs = at;
        cfg.numAttrs = 1;
        cudaLaunchKernelEx(&cfg, lstm_scan_cluster, Whh[l], (const float*)Abuf, outb[l]);
    }
    hsum_kernel<<<2048, 256>>>(hb);

    convb_kernel<<<256, 256>>>(Wmu1, Wm + 0 * 262144, 65536);
    convb_kernel<<<256, 256>>>(Wmu2, Wm + 1 * 262144, 65536);
    convb_kernel<<<256, 256>>>(Ws1,  Wm + 2 * 262144, 65536);
    convb_kernel<<<256, 256>>>(Ws2,  Wm + 3 * 262144, 65536);

    gemm_bf16_kernel<<<dim3(8, 16), 256>>>(hb, 512, Wm + 0 * 262144, 512, bmu1,
        nullptr, t1b, 512, 512, 1, nullptr, nullptr, nullptr);
    gemm_bf16_kernel<<<dim3(8, 16), 256>>>(t1b, 512, Wm + 1 * 262144, 512, bmu2,
        mu, nullptr, 512, 512, 0, nullptr, nullptr, nullptr);
    gemm_bf16_kernel<<<dim3(8, 16), 256>>>(hb, 512, Wm + 2 * 262144, 512, bs1,
        nullptr, t2b, 512, 512, 1, nullptr, nullptr, nullptr);
    gemm_bf16_kernel<<<dim3(8, 16), 256>>>(t2b, 512, Wm + 3 * 262144, 512, bs2,
        ps, nullptr, 512, 512, 0, nullptr, nullptr, nullptr);

    zkl_kernel<<<2048, 256>>>(eps, zb);
    pos_kernel<<<1024, 128>>>(en, E_en);

    gemm_bf16_kernel<<<dim3(128, 16), 256>>>(zb, 512, Gen, 512, nullptr,
        nullptr, nullptr, 0, 512, 2, nullptr, negp, nullptr);
    gemm_bf16_kernel<<<dim3(128, 16), 256>>>(zb, 512, Gfrn, 512, nullptr,
        nullptr, nullptr, 0, 512, 2, nullptr, negfp, nullptr);
    gemm_bf16_kernel<<<dim3(16, 16), 256>>>(zb, 512, Gfr, 512, nullptr,
        nullptr, nullptr, 0, 512, 3, negfp, nullptr, sumy);

    final_kernel<<<1, 256>>>((float*)d_out);
}

// round 10
// speedup vs baseline: 1.3723x; 1.3723x over previous
#include <cuda_runtime.h>
#include <cuda_bf16.h>
#include <cstdint>
#include <cstring>

#define L1N 1024
#define DN  512
#define G4  2048

__device__ float d_buf0[1024 * 1024];
__device__ float d_buf1[1024 * 1024];
__device__ float d_A[2 * 1024 * 2048];
__device__ float d_mu[1024 * 512];
__device__ float d_ps[1024 * 512];
__device__ float d_z[1024 * 512];
__device__ float d_pos[1024];
__device__ float d_neg[1024];
__device__ float d_negf[1024];
__device__ double d_kl[1];
__device__ double d_sumy[1];

__device__ __nv_bfloat16 b_Wb[2 * 2048 * 1024];
__device__ __nv_bfloat16 b_Xb[1024 * 1024];
__device__ __nv_bfloat16 b_Gen[8192 * 512];
__device__ __nv_bfloat16 b_Gfrn[8192 * 512];
__device__ __nv_bfloat16 b_Gfr[1024 * 512];
__device__ __nv_bfloat16 b_zb[1024 * 512];
__device__ __nv_bfloat16 b_hb[1024 * 512];
__device__ __nv_bfloat16 b_t1[1024 * 512];
__device__ __nv_bfloat16 b_t2[1024 * 512];
__device__ __nv_bfloat16 b_Wm[4 * 512 * 512];

__device__ __forceinline__ float sigm_f(float x) { return 1.f / (1.f + __expf(-x)); }
__device__ __forceinline__ float tanh_f(float x) {
    if (x > 10.f) return 1.f;
    if (x < -10.f) return -1.f;
    float e = __expf(2.f * x);
    return (e - 1.f) / (e + 1.f);
}
__device__ __forceinline__ uint32_t smem_u32(const void* p) {
    uint32_t a;
    asm("{ .reg .u64 t; cvta.to.shared.u64 t, %1; cvt.u32.u64 %0, t; }" : "=r"(a) : "l"(p));
    return a;
}
__device__ __forceinline__ __nv_bfloat162 as_bf2(uint32_t v) {
    __nv_bfloat162 r; memcpy(&r, &v, 4); return r;
}
__device__ __forceinline__ uint32_t packbf(float a, float b) {
    __nv_bfloat162 t = __float22bfloat162_rn(make_float2(a, b));
    uint32_t v; memcpy(&v, &t, 4); return v;
}
__device__ __forceinline__ void bar_wait_cl(uint32_t addr, uint32_t par) {
    uint32_t done;
    do {
        asm volatile("{\n\t.reg .pred p;\n\t"
            "mbarrier.try_wait.parity.acquire.cluster.shared::cta.b64 p, [%1], %2, 0x989680;\n\t"
            "selp.b32 %0, 1, 0, p;\n\t}"
            : "=r"(done) : "r"(addr), "r"(par) : "memory");
    } while (!done);
}
__device__ __forceinline__ void arrive_peer(uint32_t addr, uint32_t rank) {
    asm volatile("{\n\t.reg .b32 ra;\n\t"
        "mapa.shared::cluster.u32 ra, %0, %1;\n\t"
        "mbarrier.arrive.shared::cluster.b64 _, [ra];\n\t}"
        :: "r"(addr), "r"(rank) : "memory");
}
__device__ __forceinline__ void st_peer_v4(uint32_t addr, uint32_t peer, uint4 v) {
    asm volatile("{\n\t.reg .b32 ra;\n\t"
        "mapa.shared::cluster.u32 ra, %0, %1;\n\t"
        "st.shared::cluster.v4.u32 [ra], {%2,%3,%4,%5};\n\t}"
        :: "r"(addr), "r"(peer), "r"(v.x), "r"(v.y), "r"(v.z), "r"(v.w) : "memory");
}
__device__ __forceinline__ void ldsm_x4(uint32_t& r0, uint32_t& r1, uint32_t& r2, uint32_t& r3, uint32_t addr) {
    asm volatile("ldmatrix.sync.aligned.m8n8.x4.shared.b16 {%0,%1,%2,%3}, [%4];"
        : "=r"(r0), "=r"(r1), "=r"(r2), "=r"(r3) : "r"(addr));
}
__device__ __forceinline__ void ldsm_x2(uint32_t& r0, uint32_t& r1, uint32_t addr) {
    asm volatile("ldmatrix.sync.aligned.m8n8.x2.shared.b16 {%0,%1}, [%2];"
        : "=r"(r0), "=r"(r1) : "r"(addr));
}
__device__ __forceinline__ void mma16816(float* d, const uint32_t* a, const uint32_t* b) {
    asm volatile("mma.sync.aligned.m16n8k16.row.col.f32.bf16.bf16.f32 "
        "{%0,%1,%2,%3}, {%4,%5,%6,%7}, {%8,%9}, {%0,%1,%2,%3};"
        : "+f"(d[0]), "+f"(d[1]), "+f"(d[2]), "+f"(d[3])
        : "r"(a[0]), "r"(a[1]), "r"(a[2]), "r"(a[3]), "r"(b[0]), "r"(b[1]));
}

__global__ void reset_kernel() {
    int i = blockIdx.x * 256 + threadIdx.x;
    if (i < 1024) { d_neg[i] = 0.f; d_negf[i] = 0.f; }
    if (i == 0) { d_kl[0] = 0.0; d_sumy[0] = 0.0; }
}

__global__ void gatherb_kernel(const float* __restrict__ E, const int* __restrict__ idx,
                               __nv_bfloat16* __restrict__ dst) {
    int r = blockIdx.x, t = threadIdx.x;  // 128 threads
    float4 v = *(const float4*)(E + (size_t)idx[r] * 512 + t * 4);
    ((uint2*)(dst + (size_t)r * 512))[t] = make_uint2(packbf(v.x, v.y), packbf(v.z, v.w));
}

__global__ void convb_kernel(const float* __restrict__ src, __nv_bfloat16* __restrict__ dst, int n4) {
    int i = blockIdx.x * 256 + threadIdx.x;
    if (i < n4) {
        float4 v = ((const float4*)src)[i];
        ((uint2*)dst)[i] = make_uint2(packbf(v.x, v.y), packbf(v.z, v.w));
    }
}

__global__ void hsum_kernel(__nv_bfloat16* __restrict__ hb) {
    int i = blockIdx.x * 256 + threadIdx.x;  // 524288
    int t = i >> 9, d = i & 511;
    hb[i] = __float2bfloat16(d_buf1[t * 1024 + d] + d_buf1[t * 1024 + 512 + d]);
}

// bf16 tensor-core GEMM: C[M][N] = A[M][K] @ B[N][K]^T (fp32 accum)
__global__ __launch_bounds__(256) void gemm_bf16_kernel(
    const __nv_bfloat16* __restrict__ A, int lda,
    const __nv_bfloat16* __restrict__ B, int ldb,
    const float* __restrict__ bias,
    float* __restrict__ C, __nv_bfloat16* __restrict__ Cb, int ldc,
    int K, int mode,
    const float* __restrict__ negf,
    float* __restrict__ rowsum,
    double* __restrict__ outsum)
{
    __shared__ __align__(16) __nv_bfloat16 As[64][40];
    __shared__ __align__(16) __nv_bfloat16 Bs[64][40];
    __shared__ float red[256];

    int tid = threadIdx.x;
    int wid = tid >> 5, lane = tid & 31;
    int m0 = blockIdx.y * 64, n0 = blockIdx.x * 64;
    int wm = (wid & 1) * 32, wn = (wid >> 1) * 16;
    int lr = tid >> 2, ls = (tid & 3) * 8;

    float acc[2][2][4] = {};

    uint32_t a_addr[2], b_addr[2];
    #pragma unroll
    for (int i = 0; i < 2; ++i)
        a_addr[i] = smem_u32(&As[wm + i * 16 + (lane & 15)][(lane >> 4) * 8]);
    #pragma unroll
    for (int j = 0; j < 2; ++j)
        b_addr[j] = smem_u32(&Bs[wn + j * 8 + (lane & 7)][((lane >> 3) & 1) * 8]);

    for (int k0 = 0; k0 < K; k0 += 32) {
        *(uint4*)&As[lr][ls] = *(const uint4*)(A + (size_t)(m0 + lr) * lda + k0 + ls);
        *(uint4*)&Bs[lr][ls] = *(const uint4*)(B + (size_t)(n0 + lr) * ldb + k0 + ls);
        __syncthreads();
        #pragma unroll
        for (int kk = 0; kk < 2; ++kk) {
            uint32_t af[2][4], bf[2][2];
            #pragma unroll
            for (int i = 0; i < 2; ++i)
                ldsm_x4(af[i][0], af[i][1], af[i][2], af[i][3], a_addr[i] + kk * 32);
            #pragma unroll
            for (int j = 0; j < 2; ++j)
                ldsm_x2(bf[j][0], bf[j][1], b_addr[j] + kk * 32);
            #pragma unroll
            for (int i = 0; i < 2; ++i)
                #pragma unroll
                for (int j = 0; j < 2; ++j)
                    mma16816(acc[i][j], af[i], bf[j]);
        }
        __syncthreads();
    }

    int qr = lane >> 2, qc = (lane & 3) * 2;
    if (mode <= 1) {
        #pragma unroll
        for (int i = 0; i < 2; ++i)
            #pragma unroll
            for (int r = 0; r < 2; ++r) {
                int row = m0 + wm + i * 16 + r * 8 + qr;
                #pragma unroll
                for (int j = 0; j < 2; ++j) {
                    int col = n0 + wn + j * 8 + qc;
                    float v0 = acc[i][j][r * 2 + 0] + (bias ? bias[col] : 0.f);
                    float v1 = acc[i][j][r * 2 + 1] + (bias ? bias[col + 1] : 0.f);
                    if (mode == 1) { v0 = fmaxf(v0, 0.f); v1 = fmaxf(v1, 0.f); }
                    if (C) *(float2*)(C + (size_t)row * ldc + col) = make_float2(v0, v1);
                    if (Cb) *(uint32_t*)(Cb + (size_t)row * ldc + col) = packbf(v0, v1);
                }
            }
    } else if (mode == 2) {
        #pragma unroll
        for (int i = 0; i < 2; ++i)
            #pragma unroll
            for (int r = 0; r < 2; ++r) {
                float s = 0.f;
                #pragma unroll
                for (int j = 0; j < 2; ++j)
                    s += __expf(acc[i][j][r * 2]) + __expf(acc[i][j][r * 2 + 1]);
                s += __shfl_xor_sync(0xffffffffu, s, 1);
                s += __shfl_xor_sync(0xffffffffu, s, 2);
                if ((lane & 3) == 0)
                    atomicAdd(rowsum + m0 + wm + i * 16 + r * 8 + qr, s);
            }
    } else {
        float ssum = 0.f;
        #pragma unroll
        for (int i = 0; i < 2; ++i)
            #pragma unroll
            for (int r = 0; r < 2; ++r) {
                float nf = negf[m0 + wm + i * 16 + r * 8 + qr];
                #pragma unroll
                for (int j = 0; j < 2; ++j) {
                    float e0 = __expf(acc[i][j][r * 2]);
                    float e1 = __expf(acc[i][j][r * 2 + 1]);
                    ssum += e0 / (e0 + nf) + e1 / (e1 + nf);
                }
            }
        red[tid] = ssum;
        __syncthreads();
        for (int st = 128; st > 0; st >>= 1) {
            if (tid < st) red[tid] += red[tid + st];
            __syncthreads();
        }
        if (tid == 0) atomicAdd(outsum, (double)red[0]);
    }
}

// Cluster scan (round-8 structure): grid 32, cluster 16. dir = bx>>4, rank owns hidden [32r,32r+32).
// Whh as bf16x2 in regs. Tail entirely in warp 0; v4 DSMEM broadcast (serial depth 2).
__global__ __launch_bounds__(256, 1) void lstm_scan_cluster(
    const float* __restrict__ Whh, const float* __restrict__ Agate,
    float* __restrict__ outbuf)
{
    __shared__ uint32_t sh_hp[2][256];
    __shared__ float sh_g[128];
    __shared__ __align__(16) uint32_t sh_w[16];
    __shared__ __align__(8) uint64_t sh_bar;

    const int tid = threadIdx.x;
    const int w = tid >> 5, lane = tid & 31;
    const int half = lane >> 4, c16 = lane & 15;
    uint32_t rank;
    asm("mov.u32 %0, %%cluster_ctarank;" : "=r"(rank));
    const int dir = blockIdx.x >> 4;
    const bool fwd = (dir == 0);
    const float* Wd = Whh + (size_t)dir * G4 * DN;
    const float* Ad = Agate + (size_t)dir * L1N * G4;

    const uint32_t bar_addr = smem_u32(&sh_bar);
    const uint32_t hp0 = smem_u32(&sh_hp[0][0]);
    const uint32_t hp1 = smem_u32(&sh_hp[1][0]);

    if (tid == 0)
        asm volatile("mbarrier.init.shared.b64 [%0], %1;" :: "r"(bar_addr), "r"(16u) : "memory");
    sh_hp[1][tid] = 0u;

    uint32_t wp[8][16];
    #pragma unroll
    for (int j = 0; j < 8; ++j) {
        int r_local = 16 * w + 2 * j + half;
        int grow = (r_local >> 5) * 512 + rank * 32 + (r_local & 31);
        const float* src = Wd + (size_t)grow * DN + c16 * 32;
        #pragma unroll
        for (int q = 0; q < 8; ++q) {
            float4 v = *(const float4*)(src + q * 4);
            wp[j][2 * q]     = packbf(v.x, v.y);
            wp[j][2 * q + 1] = packbf(v.z, v.w);
        }
    }
    __syncthreads();
    asm volatile("barrier.cluster.arrive.aligned;" ::: "memory");
    asm volatile("barrier.cluster.wait.aligned;" ::: "memory");

    float c_state = 0.f;
    uint32_t parity = 0;

    for (int s = 0; s < L1N; ++s) {
        int t = fwd ? s : (L1N - 1 - s);

        float bias[8];
        if (c16 == 0) {
            #pragma unroll
            for (int j = 0; j < 8; ++j) {
                int r_local = 16 * w + 2 * j + half;
                int grow = (r_local >> 5) * 512 + rank * 32 + (r_local & 31);
                bias[j] = Ad[(size_t)t * G4 + grow];
            }
        }

        if (s > 0) { bar_wait_cl(bar_addr, parity); parity ^= 1; }

        int rb = (s + 1) & 1;
        uint32_t hvp[16];
        #pragma unroll
        for (int q = 0; q < 4; ++q) {
            uint4 v = *(const uint4*)&sh_hp[rb][c16 * 16 + q * 4];
            hvp[4 * q + 0] = v.x; hvp[4 * q + 1] = v.y;
            hvp[4 * q + 2] = v.z; hvp[4 * q + 3] = v.w;
        }

        #pragma unroll
        for (int j = 0; j < 8; ++j) {
            __nv_bfloat162 acc = __float2bfloat162_rn(0.f);
            #pragma unroll
            for (int k = 0; k < 16; ++k)
                acc = __hfma2(as_bf2(wp[j][k]), as_bf2(hvp[k]), acc);
            float sv = __low2float(acc) + __high2float(acc);
            #pragma unroll
            for (int off = 1; off < 16; off <<= 1)
                sv += __shfl_xor_sync(0xffffffffu, sv, off);
            if (c16 == 0) sh_g[16 * w + 2 * j + half] = sv + bias[j];
        }
        __syncthreads();

        if (w == 0) {
            float iv = sigm_f(sh_g[lane]);
            float fv = sigm_f(sh_g[32 + lane]);
            float gv = tanh_f(sh_g[64 + lane]);
            float ov = sigm_f(sh_g[96 + lane]);
            c_state = fv * c_state + iv * gv;
            float h = ov * tanh_f(c_state);
            outbuf[(size_t)t * 1024 + dir * 512 + rank * 32 + lane] = h;

            // stage 16 packed words in SMEM, then all 32 lanes push v4 blocks:
            // 16 peers x 4 quads = 64 v4-stores, 2 per lane (serial depth 2)
            float fe = __shfl_sync(0xffffffffu, h, 2 * c16);
            float fo = __shfl_sync(0xffffffffu, h, 2 * c16 + 1);
            if (lane < 16) sh_w[lane] = packbf(fe, fo);
            __syncwarp();
            uint32_t base = ((s & 1) ? hp1 : hp0) + rank * 64;  // 16 words * 4B
            uint4 v0 = ((const uint4*)sh_w)[2 * half];
            uint4 v1 = ((const uint4*)sh_w)[2 * half + 1];
            st_peer_v4(base + (2 * half) * 16,     (uint32_t)c16, v0);
            st_peer_v4(base + (2 * half + 1) * 16, (uint32_t)c16, v1);
            __syncwarp();
            if (lane < 16) arrive_peer(bar_addr, (uint32_t)lane);
        }
    }
    asm volatile("barrier.cluster.arrive.aligned;" ::: "memory");
    asm volatile("barrier.cluster.wait.aligned;" ::: "memory");
}

__global__ void zkl_kernel(const float* __restrict__ eps, __nv_bfloat16* __restrict__ zb) {
    int i = blockIdx.x * 256 + threadIdx.x;
    float m = d_mu[i], pre = d_ps[i];
    float sg = log1pf(expf(pre));
    float zv = fmaf(eps[i], sg, m);
    d_z[i] = zv;
    zb[i] = __float2bfloat16(zv);
    float term = 0.5f * (sg * sg + m * m - 1.f) - logf(sg);
    __shared__ float red[256];
    red[threadIdx.x] = term;
    __syncthreads();
    for (int st = 128; st > 0; st >>= 1) {
        if (threadIdx.x < st) red[threadIdx.x] += red[threadIdx.x + st];
        __syncthreads();
    }
    if (threadIdx.x == 0) atomicAdd(d_kl, (double)red[0]);
}

__global__ void pos_kernel(const int* __restrict__ en, const float* __restrict__ E) {
    int t = blockIdx.x, tid = threadIdx.x;
    float4 a = *(const float4*)(d_z + t * DN + tid * 4);
    float4 b = *(const float4*)(E + (size_t)en[t] * DN + tid * 4);
    float s = a.x * b.x + a.y * b.y + a.z * b.z + a.w * b.w;
    #pragma unroll
    for (int off = 16; off > 0; off >>= 1) s += __shfl_xor_sync(0xffffffffu, s, off);
    __shared__ float red[4];
    if ((tid & 31) == 0) red[tid >> 5] = s;
    __syncthreads();
    if (tid == 0) d_pos[t] = expf(red[0] + red[1] + red[2] + red[3]);
}

__global__ void final_kernel(float* __restrict__ out) {
    int tid = threadIdx.x;
    float sx = 0.f;
    for (int t = tid; t < 1024; t += 256) {
        float pv = d_pos[t];
        sx += pv / (pv + d_neg[t]);
    }
    __shared__ float red[256];
    red[tid] = sx;
    __syncthreads();
    for (int st = 128; st > 0; st >>= 1) {
        if (tid < st) red[tid] += red[tid + st];
        __syncthreads();
    }
    if (tid == 0) {
        float sum_y = (float)(d_sumy[0] / 1024.0);
        out[0] = -(red[0] + sum_y - (float)d_kl[0]);
    }
}

extern "C" void kernel_launch(void* const* d_in, const int* in_sizes, int n_in,
                              void* d_out, int out_size)
{
    (void)in_sizes; (void)n_in; (void)out_size;
    const int*   en     = (const int*)d_in[0];
    const int*   fr     = (const int*)d_in[1];
    const int*   en_neg = (const int*)d_in[2];
    const int*   fr_neg = (const int*)d_in[3];
    const float* emb    = (const float*)d_in[4];
    const float* Wih[3] = {(const float*)d_in[5], (const float*)d_in[8], (const float*)d_in[11]};
    const float* Whh[3] = {(const float*)d_in[6], (const float*)d_in[9], (const float*)d_in[12]};
    const float* bb[3]  = {(const float*)d_in[7], (const float*)d_in[10], (const float*)d_in[13]};
    const float* Wmu1 = (const float*)d_in[14];
    const float* bmu1 = (const float*)d_in[15];
    const float* Wmu2 = (const float*)d_in[16];
    const float* bmu2 = (const float*)d_in[17];
    const float* Ws1  = (const float*)d_in[18];
    const float* bs1  = (const float*)d_in[19];
    const float* Ws2  = (const float*)d_in[20];
    const float* bs2  = (const float*)d_in[21];
    const float* E_en = (const float*)d_in[22];
    const float* E_fr = (const float*)d_in[23];
    const float* eps  = (const float*)d_in[24];

    float *buf0, *buf1, *Abuf, *mu, *ps, *z, *negp, *negfp;
    double *sumy;
    __nv_bfloat16 *Wb, *Xb, *Gen, *Gfrn, *Gfr, *zb, *hb, *t1b, *t2b, *Wm;
    cudaGetSymbolAddress((void**)&buf0, d_buf0);
    cudaGetSymbolAddress((void**)&buf1, d_buf1);
    cudaGetSymbolAddress((void**)&Abuf, d_A);
    cudaGetSymbolAddress((void**)&mu, d_mu);
    cudaGetSymbolAddress((void**)&ps, d_ps);
    cudaGetSymbolAddress((void**)&z, d_z);
    cudaGetSymbolAddress((void**)&negp, d_neg);
    cudaGetSymbolAddress((void**)&negfp, d_negf);
    cudaGetSymbolAddress((void**)&sumy, d_sumy);
    cudaGetSymbolAddress((void**)&Wb, b_Wb);
    cudaGetSymbolAddress((void**)&Xb, b_Xb);
    cudaGetSymbolAddress((void**)&Gen, b_Gen);
    cudaGetSymbolAddress((void**)&Gfrn, b_Gfrn);
    cudaGetSymbolAddress((void**)&Gfr, b_Gfr);
    cudaGetSymbolAddress((void**)&zb, b_zb);
    cudaGetSymbolAddress((void**)&hb, b_hb);
    cudaGetSymbolAddress((void**)&t1b, b_t1);
    cudaGetSymbolAddress((void**)&t2b, b_t2);
    cudaGetSymbolAddress((void**)&Wm, b_Wm);

    cudaFuncSetAttribute(lstm_scan_cluster,
                         cudaFuncAttributeNonPortableClusterSizeAllowed, 1);

    reset_kernel<<<4, 256>>>();
    gatherb_kernel<<<1024, 128>>>(emb, en, Xb);
    gatherb_kernel<<<8192, 128>>>(E_en, en_neg, Gen);
    gatherb_kernel<<<8192, 128>>>(E_fr, fr_neg, Gfrn);
    gatherb_kernel<<<1024, 128>>>(E_fr, fr, Gfr);

    float* outb[3] = {buf1, buf0, buf1};
    int    Kl[3]   = {512, 1024, 1024};
    for (int l = 0; l < 3; ++l) {
        if (l > 0)
            convb_kernel<<<1024, 256>>>(outb[l - 1], Xb, 1024 * 1024 / 4);
        convb_kernel<<<(2 * 2048 * Kl[l] / 4 + 255) / 256, 256>>>(Wih[l], Wb, 2 * 2048 * Kl[l] / 4);
        for (int d = 0; d < 2; ++d) {
            gemm_bf16_kernel<<<dim3(32, 16), 256>>>(
                Xb, Kl[l], Wb + (size_t)d * 2048 * Kl[l], Kl[l],
                bb[l] + d * 2048,
                Abuf + (size_t)d * 1024 * 2048, nullptr, 2048, Kl[l], 0,
                nullptr, nullptr, nullptr);
        }
        cudaLaunchConfig_t cfg = {};
        cfg.gridDim = dim3(32, 1, 1);
        cfg.blockDim = dim3(256, 1, 1);
        cfg.dynamicSmemBytes = 0;
        cfg.stream = 0;
        cudaLaunchAttribute at[1];
        at[0].id = cudaLaunchAttributeClusterDimension;
        at[0].val.clusterDim.x = 16;
        at[0].val.clusterDim.y = 1;
        at[0].val.clusterDim.z = 1;
        cfg.attrs = at;
        cfg.numAttrs = 1;
        cudaLaunchKernelEx(&cfg, lstm_scan_cluster, Whh[l], (const float*)Abuf, outb[l]);
    }
    hsum_kernel<<<2048, 256>>>(hb);

    convb_kernel<<<256, 256>>>(Wmu1, Wm + 0 * 262144, 65536);
    convb_kernel<<<256, 256>>>(Wmu2, Wm + 1 * 262144, 65536);
    convb_kernel<<<256, 256>>>(Ws1,  Wm + 2 * 262144, 65536);
    convb_kernel<<<256, 256>>>(Ws2,  Wm + 3 * 262144, 65536);

    gemm_bf16_kernel<<<dim3(8, 16), 256>>>(hb, 512, Wm + 0 * 262144, 512, bmu1,
        nullptr, t1b, 512, 512, 1, nullptr, nullptr, nullptr);
    gemm_bf16_kernel<<<dim3(8, 16), 256>>>(t1b, 512, Wm + 1 * 262144, 512, bmu2,
        mu, nullptr, 512, 512, 0, nullptr, nullptr, nullptr);
    gemm_bf16_kernel<<<dim3(8, 16), 256>>>(hb, 512, Wm + 2 * 262144, 512, bs1,
        nullptr, t2b, 512, 512, 1, nullptr, nullptr, nullptr);
    gemm_bf16_kernel<<<dim3(8, 16), 256>>>(t2b, 512, Wm + 3 * 262144, 512, bs2,
        ps, nullptr, 512, 512, 0, nullptr, nullptr, nullptr);

    zkl_kernel<<<2048, 256>>>(eps, zb);
    pos_kernel<<<1024, 128>>>(en, E_en);

    gemm_bf16_kernel<<<dim3(128, 16), 256>>>(zb, 512, Gen, 512, nullptr,
        nullptr, nullptr, 0, 512, 2, nullptr, negp, nullptr);
    gemm_bf16_kernel<<<dim3(128, 16), 256>>>(zb, 512, Gfrn, 512, nullptr,
        nullptr, nullptr, 0, 512, 2, nullptr, negfp, nullptr);
    gemm_bf16_kernel<<<dim3(16, 16), 256>>>(zb, 512, Gfr, 512, nullptr,
        nullptr, nullptr, 0, 512, 3, negfp, nullptr, sumy);

    final_kernel<<<1, 256>>>((float*)d_out);
}

// round 11
// speedup vs baseline: 1.6701x; 1.2169x over previous
#include <cuda_runtime.h>
#include <cuda_bf16.h>
#include <cstdint>
#include <cstring>

#define L1N 1024
#define DN  512
#define G4  2048

__device__ float d_buf0[1024 * 1024];
__device__ float d_buf1[1024 * 1024];
__device__ float d_A[2 * 1024 * 2048];
__device__ float d_mu[1024 * 512];
__device__ float d_ps[1024 * 512];
__device__ float d_z[1024 * 512];
__device__ float d_pos[1024];
__device__ float d_neg[1024];
__device__ float d_negf[1024];
__device__ double d_kl[1];
__device__ double d_sumy[1];

__device__ __nv_bfloat16 b_Wb[2 * 2048 * 1024];
__device__ __nv_bfloat16 b_Xb[1024 * 1024];
__device__ __nv_bfloat16 b_Gen[8192 * 512];
__device__ __nv_bfloat16 b_Gfrn[8192 * 512];
__device__ __nv_bfloat16 b_Gfr[1024 * 512];
__device__ __nv_bfloat16 b_zb[1024 * 512];
__device__ __nv_bfloat16 b_hb[1024 * 512];
__device__ __nv_bfloat16 b_t1[1024 * 512];
__device__ __nv_bfloat16 b_t2[1024 * 512];
__device__ __nv_bfloat16 b_Wm[4 * 512 * 512];

__device__ __forceinline__ float tanh_t(float x) {
    float r;
    asm("tanh.approx.f32 %0, %1;" : "=f"(r) : "f"(x));
    return r;
}
__device__ __forceinline__ float sigm_t(float x) {
    return fmaf(tanh_t(0.5f * x), 0.5f, 0.5f);
}
__device__ __forceinline__ uint32_t smem_u32(const void* p) {
    uint32_t a;
    asm("{ .reg .u64 t; cvta.to.shared.u64 t, %1; cvt.u32.u64 %0, t; }" : "=r"(a) : "l"(p));
    return a;
}
__device__ __forceinline__ __nv_bfloat162 as_bf2(uint32_t v) {
    __nv_bfloat162 r; memcpy(&r, &v, 4); return r;
}
__device__ __forceinline__ uint32_t packbf(float a, float b) {
    __nv_bfloat162 t = __float22bfloat162_rn(make_float2(a, b));
    uint32_t v; memcpy(&v, &t, 4); return v;
}
__device__ __forceinline__ void bar_wait_cl(uint32_t addr, uint32_t par) {
    uint32_t done;
    do {
        asm volatile("{\n\t.reg .pred p;\n\t"
            "mbarrier.try_wait.parity.acquire.cluster.shared::cta.b64 p, [%1], %2, 0x989680;\n\t"
            "selp.b32 %0, 1, 0, p;\n\t}"
            : "=r"(done) : "r"(addr), "r"(par) : "memory");
    } while (!done);
}
__device__ __forceinline__ void arrive_peer(uint32_t addr, uint32_t rank) {
    asm volatile("{\n\t.reg .b32 ra;\n\t"
        "mapa.shared::cluster.u32 ra, %0, %1;\n\t"
        "mbarrier.arrive.shared::cluster.b64 _, [ra];\n\t}"
        :: "r"(addr), "r"(rank) : "memory");
}
__device__ __forceinline__ void st_peer_v4(uint32_t addr, uint32_t peer, uint4 v) {
    asm volatile("{\n\t.reg .b32 ra;\n\t"
        "mapa.shared::cluster.u32 ra, %0, %1;\n\t"
        "st.shared::cluster.v4.u32 [ra], {%2,%3,%4,%5};\n\t}"
        :: "r"(addr), "r"(peer), "r"(v.x), "r"(v.y), "r"(v.z), "r"(v.w) : "memory");
}
__device__ __forceinline__ void ldsm_x4(uint32_t& r0, uint32_t& r1, uint32_t& r2, uint32_t& r3, uint32_t addr) {
    asm volatile("ldmatrix.sync.aligned.m8n8.x4.shared.b16 {%0,%1,%2,%3}, [%4];"
        : "=r"(r0), "=r"(r1), "=r"(r2), "=r"(r3) : "r"(addr));
}
__device__ __forceinline__ void ldsm_x2(uint32_t& r0, uint32_t& r1, uint32_t addr) {
    asm volatile("ldmatrix.sync.aligned.m8n8.x2.shared.b16 {%0,%1}, [%2];"
        : "=r"(r0), "=r"(r1) : "r"(addr));
}
__device__ __forceinline__ void mma16816(float* d, const uint32_t* a, const uint32_t* b) {
    asm volatile("mma.sync.aligned.m16n8k16.row.col.f32.bf16.bf16.f32 "
        "{%0,%1,%2,%3}, {%4,%5,%6,%7}, {%8,%9}, {%0,%1,%2,%3};"
        : "+f"(d[0]), "+f"(d[1]), "+f"(d[2]), "+f"(d[3])
        : "r"(a[0]), "r"(a[1]), "r"(a[2]), "r"(a[3]), "r"(b[0]), "r"(b[1]));
}

__global__ void reset_kernel() {
    int i = blockIdx.x * 256 + threadIdx.x;
    if (i < 1024) { d_neg[i] = 0.f; d_negf[i] = 0.f; }
    if (i == 0) { d_kl[0] = 0.0; d_sumy[0] = 0.0; }
}

__global__ void gatherb_kernel(const float* __restrict__ E, const int* __restrict__ idx,
                               __nv_bfloat16* __restrict__ dst) {
    int r = blockIdx.x, t = threadIdx.x;  // 128 threads
    float4 v = *(const float4*)(E + (size_t)idx[r] * 512 + t * 4);
    ((uint2*)(dst + (size_t)r * 512))[t] = make_uint2(packbf(v.x, v.y), packbf(v.z, v.w));
}

__global__ void convb_kernel(const float* __restrict__ src, __nv_bfloat16* __restrict__ dst, int n4) {
    int i = blockIdx.x * 256 + threadIdx.x;
    if (i < n4) {
        float4 v = ((const float4*)src)[i];
        ((uint2*)dst)[i] = make_uint2(packbf(v.x, v.y), packbf(v.z, v.w));
    }
}

__global__ void hsum_kernel(__nv_bfloat16* __restrict__ hb) {
    int i = blockIdx.x * 256 + threadIdx.x;  // 524288
    int t = i >> 9, d = i & 511;
    hb[i] = __float2bfloat16(d_buf1[t * 1024 + d] + d_buf1[t * 1024 + 512 + d]);
}

// bf16 tensor-core GEMM: C[M][N] = A[M][K] @ B[N][K]^T (fp32 accum)
__global__ __launch_bounds__(256) void gemm_bf16_kernel(
    const __nv_bfloat16* __restrict__ A, int lda,
    const __nv_bfloat16* __restrict__ B, int ldb,
    const float* __restrict__ bias,
    float* __restrict__ C, __nv_bfloat16* __restrict__ Cb, int ldc,
    int K, int mode,
    const float* __restrict__ negf,
    float* __restrict__ rowsum,
    double* __restrict__ outsum)
{
    __shared__ __align__(16) __nv_bfloat16 As[64][40];
    __shared__ __align__(16) __nv_bfloat16 Bs[64][40];
    __shared__ float red[256];

    int tid = threadIdx.x;
    int wid = tid >> 5, lane = tid & 31;
    int m0 = blockIdx.y * 64, n0 = blockIdx.x * 64;
    int wm = (wid & 1) * 32, wn = (wid >> 1) * 16;
    int lr = tid >> 2, ls = (tid & 3) * 8;

    float acc[2][2][4] = {};

    uint32_t a_addr[2], b_addr[2];
    #pragma unroll
    for (int i = 0; i < 2; ++i)
        a_addr[i] = smem_u32(&As[wm + i * 16 + (lane & 15)][(lane >> 4) * 8]);
    #pragma unroll
    for (int j = 0; j < 2; ++j)
        b_addr[j] = smem_u32(&Bs[wn + j * 8 + (lane & 7)][((lane >> 3) & 1) * 8]);

    for (int k0 = 0; k0 < K; k0 += 32) {
        *(uint4*)&As[lr][ls] = *(const uint4*)(A + (size_t)(m0 + lr) * lda + k0 + ls);
        *(uint4*)&Bs[lr][ls] = *(const uint4*)(B + (size_t)(n0 + lr) * ldb + k0 + ls);
        __syncthreads();
        #pragma unroll
        for (int kk = 0; kk < 2; ++kk) {
            uint32_t af[2][4], bf[2][2];
            #pragma unroll
            for (int i = 0; i < 2; ++i)
                ldsm_x4(af[i][0], af[i][1], af[i][2], af[i][3], a_addr[i] + kk * 32);
            #pragma unroll
            for (int j = 0; j < 2; ++j)
                ldsm_x2(bf[j][0], bf[j][1], b_addr[j] + kk * 32);
            #pragma unroll
            for (int i = 0; i < 2; ++i)
                #pragma unroll
                for (int j = 0; j < 2; ++j)
                    mma16816(acc[i][j], af[i], bf[j]);
        }
        __syncthreads();
    }

    int qr = lane >> 2, qc = (lane & 3) * 2;
    if (mode <= 1) {
        #pragma unroll
        for (int i = 0; i < 2; ++i)
            #pragma unroll
            for (int r = 0; r < 2; ++r) {
                int row = m0 + wm + i * 16 + r * 8 + qr;
                #pragma unroll
                for (int j = 0; j < 2; ++j) {
                    int col = n0 + wn + j * 8 + qc;
                    float v0 = acc[i][j][r * 2 + 0] + (bias ? bias[col] : 0.f);
                    float v1 = acc[i][j][r * 2 + 1] + (bias ? bias[col + 1] : 0.f);
                    if (mode == 1) { v0 = fmaxf(v0, 0.f); v1 = fmaxf(v1, 0.f); }
                    if (C) *(float2*)(C + (size_t)row * ldc + col) = make_float2(v0, v1);
                    if (Cb) *(uint32_t*)(Cb + (size_t)row * ldc + col) = packbf(v0, v1);
                }
            }
    } else if (mode == 2) {
        #pragma unroll
        for (int i = 0; i < 2; ++i)
            #pragma unroll
            for (int r = 0; r < 2; ++r) {
                float s = 0.f;
                #pragma unroll
                for (int j = 0; j < 2; ++j)
                    s += __expf(acc[i][j][r * 2]) + __expf(acc[i][j][r * 2 + 1]);
                s += __shfl_xor_sync(0xffffffffu, s, 1);
                s += __shfl_xor_sync(0xffffffffu, s, 2);
                if ((lane & 3) == 0)
                    atomicAdd(rowsum + m0 + wm + i * 16 + r * 8 + qr, s);
            }
    } else {
        float ssum = 0.f;
        #pragma unroll
        for (int i = 0; i < 2; ++i)
            #pragma unroll
            for (int r = 0; r < 2; ++r) {
                float nf = negf[m0 + wm + i * 16 + r * 8 + qr];
                #pragma unroll
                for (int j = 0; j < 2; ++j) {
                    float e0 = __expf(acc[i][j][r * 2]);
                    float e1 = __expf(acc[i][j][r * 2 + 1]);
                    ssum += e0 / (e0 + nf) + e1 / (e1 + nf);
                }
            }
        red[tid] = ssum;
        __syncthreads();
        for (int st = 128; st > 0; st >>= 1) {
            if (tid < st) red[tid] += red[tid + st];
            __syncthreads();
        }
        if (tid == 0) atomicAdd(outsum, (double)red[0]);
    }
}

// Cluster scan: grid 32, cluster 16. dir = bx>>4, rank owns hidden [32r,32r+32).
// Row mapping: local row idx = 2j+half (j=0..7, half=lane>>4); gate = idx>>2, unit-in-4 = idx&3.
// Warp w owns units 4w..4w+3 (all 4 gates). Gate-lane (c16<2) handles unit uu=2*c16+half
// using its OWN sv[c16], sv[c16+2], sv[c16+4], sv[c16+6]. No pre-gate barrier.
__global__ __launch_bounds__(256, 1) void lstm_scan_cluster(
    const float* __restrict__ Whh, const float* __restrict__ Agate,
    float* __restrict__ outbuf, __nv_bfloat16* __restrict__ xout)
{
    __shared__ uint32_t sh_hp[2][256];
    __shared__ __align__(16) __nv_bfloat16 sh_wb[32];
    __shared__ __align__(8) uint64_t sh_bar;

    const int tid = threadIdx.x;
    const int w = tid >> 5, lane = tid & 31;
    const int half = lane >> 4, c16 = lane & 15;
    uint32_t rank;
    asm("mov.u32 %0, %%cluster_ctarank;" : "=r"(rank));
    const int dir = blockIdx.x >> 4;
    const bool fwd = (dir == 0);
    const float* Wd = Whh + (size_t)dir * G4 * DN;
    const float* Ad = Agate + (size_t)dir * L1N * G4;

    const uint32_t bar_addr = smem_u32(&sh_bar);
    const uint32_t hp0 = smem_u32(&sh_hp[0][0]);
    const uint32_t hp1 = smem_u32(&sh_hp[1][0]);

    if (tid == 0)
        asm volatile("mbarrier.init.shared.b64 [%0], %1;" :: "r"(bar_addr), "r"(16u) : "memory");
    sh_hp[1][tid] = 0u;

    // weights: rows idx=2j+half -> grow = (idx>>2)*512 + rank*32 + 4w + (idx&3)
    uint32_t wp[8][16];
    #pragma unroll
    for (int j = 0; j < 8; ++j) {
        int idx = 2 * j + half;
        int grow = (idx >> 2) * 512 + rank * 32 + 4 * w + (idx & 3);
        const float* src = Wd + (size_t)grow * DN + c16 * 32;
        #pragma unroll
        for (int q = 0; q < 8; ++q) {
            float4 v = *(const float4*)(src + q * 4);
            wp[j][2 * q]     = packbf(v.x, v.y);
            wp[j][2 * q + 1] = packbf(v.z, v.w);
        }
    }
    const int unit = 4 * w + 2 * c16 + half;      // valid for c16 < 2
    const int brow = rank * 32 + unit;            // hidden index for bias rows
    __syncthreads();
    asm volatile("barrier.cluster.arrive.aligned;" ::: "memory");
    asm volatile("barrier.cluster.wait.aligned;" ::: "memory");

    float c_state = 0.f;
    uint32_t parity = 0;

    for (int s = 0; s < L1N; ++s) {
        int t = fwd ? s : (L1N - 1 - s);

        float bias[4];
        if (c16 < 2) {
            #pragma unroll
            for (int g = 0; g < 4; ++g)
                bias[g] = Ad[(size_t)t * G4 + g * 512 + brow];
        }

        if (s > 0) { bar_wait_cl(bar_addr, parity); parity ^= 1; }

        int rb = (s + 1) & 1;
        uint32_t hvp[16];
        #pragma unroll
        for (int q = 0; q < 4; ++q) {
            uint4 v = *(const uint4*)&sh_hp[rb][c16 * 16 + q * 4];
            hvp[4 * q + 0] = v.x; hvp[4 * q + 1] = v.y;
            hvp[4 * q + 2] = v.z; hvp[4 * q + 3] = v.w;
        }

        float sv[8];
        #pragma unroll
        for (int j = 0; j < 8; ++j) {
            __nv_bfloat162 acc = __float2bfloat162_rn(0.f);
            #pragma unroll
            for (int k = 0; k < 16; ++k)
                acc = __hfma2(as_bf2(wp[j][k]), as_bf2(hvp[k]), acc);
            float s0 = __low2float(acc) + __high2float(acc);
            s0 += __shfl_xor_sync(0xffffffffu, s0, 1);
            s0 += __shfl_xor_sync(0xffffffffu, s0, 2);
            s0 += __shfl_xor_sync(0xffffffffu, s0, 4);
            s0 += __shfl_xor_sync(0xffffffffu, s0, 8);
            sv[j] = s0;
        }

        if (c16 < 2) {
            float iv = sigm_t(sv[c16]     + bias[0]);
            float fv = sigm_t(sv[c16 + 2] + bias[1]);
            float gv = tanh_t(sv[c16 + 4] + bias[2]);
            float ov = sigm_t(sv[c16 + 6] + bias[3]);
            c_state = fv * c_state + iv * gv;
            float h = ov * tanh_t(c_state);
            __nv_bfloat16 hb16 = __float2bfloat16(h);
            sh_wb[unit] = hb16;
            size_t off = (size_t)t * 1024 + dir * 512 + rank * 32 + unit;
            outbuf[off] = h;
            xout[off] = hb16;
        }
        __syncthreads();

        if (w == 0) {
            uint32_t base = ((s & 1) ? hp1 : hp0) + rank * 64;
            uint4 v0 = ((const uint4*)sh_wb)[2 * half];
            uint4 v1 = ((const uint4*)sh_wb)[2 * half + 1];
            st_peer_v4(base + (2 * half) * 16,     (uint32_t)c16, v0);
            st_peer_v4(base + (2 * half + 1) * 16, (uint32_t)c16, v1);
            __syncwarp();
            if (lane < 16) arrive_peer(bar_addr, (uint32_t)lane);
        }
    }
    asm volatile("barrier.cluster.arrive.aligned;" ::: "memory");
    asm volatile("barrier.cluster.wait.aligned;" ::: "memory");
}

__global__ void zkl_kernel(const float* __restrict__ eps, __nv_bfloat16* __restrict__ zb) {
    int i = blockIdx.x * 256 + threadIdx.x;
    float m = d_mu[i], pre = d_ps[i];
    float sg = log1pf(expf(pre));
    float zv = fmaf(eps[i], sg, m);
    d_z[i] = zv;
    zb[i] = __float2bfloat16(zv);
    float term = 0.5f * (sg * sg + m * m - 1.f) - logf(sg);
    __shared__ float red[256];
    red[threadIdx.x] = term;
    __syncthreads();
    for (int st = 128; st > 0; st >>= 1) {
        if (threadIdx.x < st) red[threadIdx.x] += red[threadIdx.x + st];
        __syncthreads();
    }
    if (threadIdx.x == 0) atomicAdd(d_kl, (double)red[0]);
}

__global__ void pos_kernel(const int* __restrict__ en, const float* __restrict__ E) {
    int t = blockIdx.x, tid = threadIdx.x;
    float4 a = *(const float4*)(d_z + t * DN + tid * 4);
    float4 b = *(const float4*)(E + (size_t)en[t] * DN + tid * 4);
    float s = a.x * b.x + a.y * b.y + a.z * b.z + a.w * b.w;
    #pragma unroll
    for (int off = 16; off > 0; off >>= 1) s += __shfl_xor_sync(0xffffffffu, s, off);
    __shared__ float red[4];
    if ((tid & 31) == 0) red[tid >> 5] = s;
    __syncthreads();
    if (tid == 0) d_pos[t] = expf(red[0] + red[1] + red[2] + red[3]);
}

__global__ void final_kernel(float* __restrict__ out) {
    int tid = threadIdx.x;
    float sx = 0.f;
    for (int t = tid; t < 1024; t += 256) {
        float pv = d_pos[t];
        sx += pv / (pv + d_neg[t]);
    }
    __shared__ float red[256];
    red[tid] = sx;
    __syncthreads();
    for (int st = 128; st > 0; st >>= 1) {
        if (tid < st) red[tid] += red[tid + st];
        __syncthreads();
    }
    if (tid == 0) {
        float sum_y = (float)(d_sumy[0] / 1024.0);
        out[0] = -(red[0] + sum_y - (float)d_kl[0]);
    }
}

extern "C" void kernel_launch(void* const* d_in, const int* in_sizes, int n_in,
                              void* d_out, int out_size)
{
    (void)in_sizes; (void)n_in; (void)out_size;
    const int*   en     = (const int*)d_in[0];
    const int*   fr     = (const int*)d_in[1];
    const int*   en_neg = (const int*)d_in[2];
    const int*   fr_neg = (const int*)d_in[3];
    const float* emb    = (const float*)d_in[4];
    const float* Wih[3] = {(const float*)d_in[5], (const float*)d_in[8], (const float*)d_in[11]};
    const float* Whh[3] = {(const float*)d_in[6], (const float*)d_in[9], (const float*)d_in[12]};
    const float* bb[3]  = {(const float*)d_in[7], (const float*)d_in[10], (const float*)d_in[13]};
    const float* Wmu1 = (const float*)d_in[14];
    const float* bmu1 = (const float*)d_in[15];
    const float* Wmu2 = (const float*)d_in[16];
    const float* bmu2 = (const float*)d_in[17];
    const float* Ws1  = (const float*)d_in[18];
    const float* bs1  = (const float*)d_in[19];
    const float* Ws2  = (const float*)d_in[20];
    const float* bs2  = (const float*)d_in[21];
    const float* E_en = (const float*)d_in[22];
    const float* E_fr = (const float*)d_in[23];
    const float* eps  = (const float*)d_in[24];

    float *buf0, *buf1, *Abuf, *mu, *ps, *z, *negp, *negfp;
    double *sumy;
    __nv_bfloat16 *Wb, *Xb, *Gen, *Gfrn, *Gfr, *zb, *hb, *t1b, *t2b, *Wm;
    cudaGetSymbolAddress((void**)&buf0, d_buf0);
    cudaGetSymbolAddress((void**)&buf1, d_buf1);
    cudaGetSymbolAddress((void**)&Abuf, d_A);
    cudaGetSymbolAddress((void**)&mu, d_mu);
    cudaGetSymbolAddress((void**)&ps, d_ps);
    cudaGetSymbolAddress((void**)&z, d_z);
    cudaGetSymbolAddress((void**)&negp, d_neg);
    cudaGetSymbolAddress((void**)&negfp, d_negf);
    cudaGetSymbolAddress((void**)&sumy, d_sumy);
    cudaGetSymbolAddress((void**)&Wb, b_Wb);
    cudaGetSymbolAddress((void**)&Xb, b_Xb);
    cudaGetSymbolAddress((void**)&Gen, b_Gen);
    cudaGetSymbolAddress((void**)&Gfrn, b_Gfrn);
    cudaGetSymbolAddress((void**)&Gfr, b_Gfr);
    cudaGetSymbolAddress((void**)&zb, b_zb);
    cudaGetSymbolAddress((void**)&hb, b_hb);
    cudaGetSymbolAddress((void**)&t1b, b_t1);
    cudaGetSymbolAddress((void**)&t2b, b_t2);
    cudaGetSymbolAddress((void**)&Wm, b_Wm);

    cudaFuncSetAttribute(lstm_scan_cluster,
                         cudaFuncAttributeNonPortableClusterSizeAllowed, 1);

    reset_kernel<<<4, 256>>>();
    gatherb_kernel<<<1024, 128>>>(emb, en, Xb);
    gatherb_kernel<<<8192, 128>>>(E_en, en_neg, Gen);
    gatherb_kernel<<<8192, 128>>>(E_fr, fr_neg, Gfrn);
    gatherb_kernel<<<1024, 128>>>(E_fr, fr, Gfr);

    float* outb[3] = {buf1, buf0, buf1};
    int    Kl[3]   = {512, 1024, 1024};
    for (int l = 0; l < 3; ++l) {
        convb_kernel<<<(2 * 2048 * Kl[l] / 4 + 255) / 256, 256>>>(Wih[l], Wb, 2 * 2048 * Kl[l] / 4);
        for (int d = 0; d < 2; ++d) {
            gemm_bf16_kernel<<<dim3(32, 16), 256>>>(
                Xb, Kl[l], Wb + (size_t)d * 2048 * Kl[l], Kl[l],
                bb[l] + d * 2048,
                Abuf + (size_t)d * 1024 * 2048, nullptr, 2048, Kl[l], 0,
                nullptr, nullptr, nullptr);
        }
        cudaLaunchConfig_t cfg = {};
        cfg.gridDim = dim3(32, 1, 1);
        cfg.blockDim = dim3(256, 1, 1);
        cfg.dynamicSmemBytes = 0;
        cfg.stream = 0;
        cudaLaunchAttribute at[1];
        at[0].id = cudaLaunchAttributeClusterDimension;
        at[0].val.clusterDim.x = 16;
        at[0].val.clusterDim.y = 1;
        at[0].val.clusterDim.z = 1;
        cfg.attrs = at;
        cfg.numAttrs = 1;
        // scan writes fp32 h to outb[l] and bf16 h to Xb (next layer's GEMM input)
        cudaLaunchKernelEx(&cfg, lstm_scan_cluster, Whh[l], (const float*)Abuf, outb[l], Xb);
    }
    hsum_kernel<<<2048, 256>>>(hb);

    convb_kernel<<<256, 256>>>(Wmu1, Wm + 0 * 262144, 65536);
    convb_kernel<<<256, 256>>>(Wmu2, Wm + 1 * 262144, 65536);
    convb_kernel<<<256, 256>>>(Ws1,  Wm + 2 * 262144, 65536);
    convb_kernel<<<256, 256>>>(Ws2,  Wm + 3 * 262144, 65536);

    gemm_bf16_kernel<<<dim3(8, 16), 256>>>(hb, 512, Wm + 0 * 262144, 512, bmu1,
        nullptr, t1b, 512, 512, 1, nullptr, nullptr, nullptr);
    gemm_bf16_kernel<<<dim3(8, 16), 256>>>(t1b, 512, Wm + 1 * 262144, 512, bmu2,
        mu, nullptr, 512, 512, 0, nullptr, nullptr, nullptr);
    gemm_bf16_kernel<<<dim3(8, 16), 256>>>(hb, 512, Wm + 2 * 262144, 512, bs1,
        nullptr, t2b, 512, 512, 1, nullptr, nullptr, nullptr);
    gemm_bf16_kernel<<<dim3(8, 16), 256>>>(t2b, 512, Wm + 3 * 262144, 512, bs2,
        ps, nullptr, 512, 512, 0, nullptr, nullptr, nullptr);

    zkl_kernel<<<2048, 256>>>(eps, zb);
    pos_kernel<<<1024, 128>>>(en, E_en);

    gemm_bf16_kernel<<<dim3(128, 16), 256>>>(zb, 512, Gen, 512, nullptr,
        nullptr, nullptr, 0, 512, 2, nullptr, negp, nullptr);
    gemm_bf16_kernel<<<dim3(128, 16), 256>>>(zb, 512, Gfrn, 512, nullptr,
        nullptr, nullptr, 0, 512, 2, nullptr, negfp, nullptr);
    gemm_bf16_kernel<<<dim3(16, 16), 256>>>(zb, 512, Gfr, 512, nullptr,
        nullptr, nullptr, 0, 512, 3, negfp, nullptr, sumy);

    final_kernel<<<1, 256>>>((float*)d_out);
}